// round 15
// baseline (speedup 1.0000x reference)
#include <cuda_runtime.h>
#include <cuda_bf16.h>
#include <cuda_fp16.h>
#include <cstdint>

constexpr int CC = 128, HH = 128, WW = 128, HW = HH * WW;
constexpr int NWIN = 31, NPP = NWIN * NWIN, NPATCH = 8 * NPP;   // 7688
constexpr float SCALE = 0.08838834764831845f;                    // 128^-0.5

constexpr int QHc = 0, QLc = 8192, KHc = 16384, KLc = 24576;
constexpr int VHo = 0, VLo = 16384, TBo = 32768;
constexpr int TBU_S = 34;
constexpr int SMEM_TOTAL = TBo + 64 * TBU_S * 4;                 // 41472 -> 5 CTAs/SM

__device__ __half g_zbuf[(size_t)NPATCH * 64 * 128];             // [patch][t][c], fp16
__device__ __half g_zpad[128];                                   // zeros for edge contributors

__device__ __forceinline__ uint32_t smem_u32(const void* p) {
    uint32_t a;
    asm("{ .reg .u64 t; cvta.to.shared.u64 t, %1; cvt.u32.u64 %0, t; }" : "=r"(a) : "l"(p));
    return a;
}
__device__ __forceinline__ uint32_t sw128(uint32_t off) { return off ^ ((off >> 3) & 0x70); }
__device__ __forceinline__ void sts64(uint32_t a, uint32_t v0, uint32_t v1) {
    asm volatile("st.shared.v2.b32 [%0], {%1, %2};" :: "r"(a), "r"(v0), "r"(v1) : "memory");
}
__device__ __forceinline__ void ldsm4t(uint32_t r[4], uint32_t a) {
    asm volatile("ldmatrix.sync.aligned.m8n8.x4.trans.shared.b16 {%0,%1,%2,%3}, [%4];"
                 : "=r"(r[0]), "=r"(r[1]), "=r"(r[2]), "=r"(r[3]) : "r"(a));
}
__device__ __forceinline__ void ldsm4(uint32_t r[4], uint32_t a) {
    asm volatile("ldmatrix.sync.aligned.m8n8.x4.shared.b16 {%0,%1,%2,%3}, [%4];"
                 : "=r"(r[0]), "=r"(r[1]), "=r"(r[2]), "=r"(r[3]) : "r"(a));
}
__device__ __forceinline__ void mma16816(float c[4], const uint32_t a[4], const uint32_t b[2]) {
    asm volatile(
        "mma.sync.aligned.m16n8k16.row.col.f32.bf16.bf16.f32 "
        "{%0,%1,%2,%3}, {%4,%5,%6,%7}, {%8,%9}, {%0,%1,%2,%3};"
        : "+f"(c[0]), "+f"(c[1]), "+f"(c[2]), "+f"(c[3])
        : "r"(a[0]), "r"(a[1]), "r"(a[2]), "r"(a[3]), "r"(b[0]), "r"(b[1]));
}
__device__ __forceinline__ uint32_t pack2h(float x, float y) {
    __half2 h = __floats2half2_rn(x, y);
    return *reinterpret_cast<uint32_t*>(&h);
}
__device__ __forceinline__ void split2(float x, float y, uint32_t& hi, uint32_t& lo) {
    __nv_bfloat162 h = __floats2bfloat162_rn(x, y);
    float2 hf = __bfloat1622float2(h);
    __nv_bfloat162 l = __floats2bfloat162_rn(x - hf.x, y - hf.y);
    hi = *reinterpret_cast<uint32_t*>(&h);
    lo = *reinterpret_cast<uint32_t*>(&l);
}

__global__ __launch_bounds__(128, 5)
void attn_kernel(const float* __restrict__ q, const float* __restrict__ k,
                 const float* __restrict__ v)
{
    extern __shared__ char smem[];
    const uint32_t sb = smem_u32(smem);
    const int tid = threadIdx.x, wp = tid >> 5, lane = tid & 31;
    const int g = blockIdx.x;
    const int b = g / NPP, rr = g - b * NPP;
    const int h0 = (rr / NWIN) * 4, w0 = (rr % NWIN) * 4;
    const size_t pbase = (size_t)b * CC * HW + (size_t)h0 * WW + w0;

    const int r8 = lane & 7, mi4 = lane >> 3;
    const int dmA = (mi4 & 1) << 3, dkA = (mi4 & 2) << 2;
    const uint32_t aXor = ((uint32_t)(32 * wp + 2 * dmA)) ^ ((uint32_t)r8 << 4);
    const int rowB = ((lane >> 3) & 1) * 8 + r8;
    const int ntSel = lane >> 4;
    const uint32_t rXor = (uint32_t)r8 << 4;

    float s[8][4];
#pragma unroll
    for (int i = 0; i < 8; ++i)
#pragma unroll
        for (int j = 0; j < 4; ++j) s[i][j] = 0.f;

    // ================= phase 1: S = Q K^T, two 64-channel chunks =================
    for (int ck = 0; ck < 2; ++ck) {
#pragma unroll
        for (int it = 0; it < 8; ++it) {
            int idx = tid + (it << 7);
            int cL = idx >> 4, t0 = (idx & 15) << 2;
            int c = ck * 64 + cL;
            size_t gp = pbase + (size_t)c * HW + (size_t)(t0 >> 3) * WW + (t0 & 7);
            float4 qv = *(const float4*)(q + gp);
            float4 kv = *(const float4*)(k + gp);
            uint32_t qh0, ql0, qh1, ql1, kh0, kl0, kh1, kl1;
            split2(qv.x * SCALE, qv.y * SCALE, qh0, ql0);
            split2(qv.z * SCALE, qv.w * SCALE, qh1, ql1);
            split2(kv.x, kv.y, kh0, kl0);
            split2(kv.z, kv.w, kh1, kl1);
            uint32_t off = sw128((uint32_t)(cL * 128 + t0 * 2));
            sts64(sb + QHc + off, qh0, qh1);
            sts64(sb + QLc + off, ql0, ql1);
            sts64(sb + KHc + off, kh0, kh1);
            sts64(sb + KLc + off, kl0, kl1);
        }
        __syncthreads();
#pragma unroll
        for (int kt = 0; kt < 4; ++kt) {
            uint32_t ah[4], al[4];
            uint32_t aA = sb + QHc + (uint32_t)((kt * 16 + dkA + r8) * 128) + aXor;
            ldsm4t(ah, aA);
            ldsm4t(al, aA + (QLc - QHc));
            uint32_t bRowA = sb + KHc + (uint32_t)((kt * 16 + rowB) * 128);
#pragma unroll
            for (int ntp = 0; ntp < 4; ++ntp) {
                uint32_t bh4[4], bl4[4];
                uint32_t baddr = bRowA + ((((uint32_t)(ntp * 2 + ntSel)) << 4) ^ rXor);
                ldsm4t(bh4, baddr);
                ldsm4t(bl4, baddr + (KLc - KHc));
                mma16816(s[2 * ntp], ah, bh4);
                mma16816(s[2 * ntp], ah, bl4);
                mma16816(s[2 * ntp], al, bh4);
                mma16816(s[2 * ntp + 1], ah, bh4 + 2);
                mma16816(s[2 * ntp + 1], ah, bl4 + 2);
                mma16816(s[2 * ntp + 1], al, bh4 + 2);
            }
        }
        __syncthreads();
    }

    // ---- load V [c][s] hi/lo (aliases phase-1 buffers) ----
#pragma unroll
    for (int it = 0; it < 16; ++it) {
        int idx = tid + (it << 7);
        int c = idx >> 4, t0 = (idx & 15) << 2;
        size_t gp = pbase + (size_t)c * HW + (size_t)(t0 >> 3) * WW + (t0 & 7);
        float4 vv = *(const float4*)(v + gp);
        uint32_t vh0, vl0, vh1, vl1;
        split2(vv.x, vv.y, vh0, vl0);
        split2(vv.z, vv.w, vh1, vl1);
        uint32_t off = sw128((uint32_t)(c * 128 + t0 * 2));
        sts64(sb + VHo + off, vh0, vh1);
        sts64(sb + VLo + off, vl0, vl1);
    }

    // ---- softmax in registers (row lives in 4 lanes) ----
    float mx0 = -1e30f, mx1 = -1e30f;
#pragma unroll
    for (int nt = 0; nt < 8; ++nt) {
        mx0 = fmaxf(mx0, fmaxf(s[nt][0], s[nt][1]));
        mx1 = fmaxf(mx1, fmaxf(s[nt][2], s[nt][3]));
    }
    mx0 = fmaxf(mx0, __shfl_xor_sync(~0u, mx0, 1));
    mx0 = fmaxf(mx0, __shfl_xor_sync(~0u, mx0, 2));
    mx1 = fmaxf(mx1, __shfl_xor_sync(~0u, mx1, 1));
    mx1 = fmaxf(mx1, __shfl_xor_sync(~0u, mx1, 2));
    float sm0 = 0.f, sm1 = 0.f;
#pragma unroll
    for (int nt = 0; nt < 8; ++nt) {
        s[nt][0] = __expf(s[nt][0] - mx0);
        s[nt][1] = __expf(s[nt][1] - mx0);
        s[nt][2] = __expf(s[nt][2] - mx1);
        s[nt][3] = __expf(s[nt][3] - mx1);
        sm0 += s[nt][0] + s[nt][1];
        sm1 += s[nt][2] + s[nt][3];
    }
    sm0 += __shfl_xor_sync(~0u, sm0, 1);
    sm0 += __shfl_xor_sync(~0u, sm0, 2);
    sm1 += __shfl_xor_sync(~0u, sm1, 1);
    sm1 += __shfl_xor_sync(~0u, sm1, 2);
    const float inv0 = 1.f / sm0, inv1 = 1.f / sm1;

    // ---- P fragments: split ONCE (s dies here, before z goes live) ----
    uint32_t pfh[16], pfl[16];
#pragma unroll
    for (int kt = 0; kt < 4; ++kt) {
        split2(s[2 * kt][0] * inv0, s[2 * kt][1] * inv0, pfh[4 * kt + 0], pfl[4 * kt + 0]);
        split2(s[2 * kt][2] * inv1, s[2 * kt][3] * inv1, pfh[4 * kt + 1], pfl[4 * kt + 1]);
        split2(s[2 * kt + 1][0] * inv0, s[2 * kt + 1][1] * inv0, pfh[4 * kt + 2], pfl[4 * kt + 2]);
        split2(s[2 * kt + 1][2] * inv1, s[2 * kt + 1][3] * inv1, pfh[4 * kt + 3], pfl[4 * kt + 3]);
    }
    __syncthreads();   // V visible

    // ================= phase 2: Z = P V, two 64-channel halves =================
    uint32_t* tbu = reinterpret_cast<uint32_t*>(smem + TBo);
    __half* zg = g_zbuf + (size_t)g * 8192;
    const int trow = 16 * wp + (lane >> 2);

    for (int hv = 0; hv < 2; ++hv) {
        float z[8][4];
#pragma unroll
        for (int i = 0; i < 8; ++i)
#pragma unroll
            for (int j = 0; j < 4; ++j) z[i][j] = 0.f;

#pragma unroll
        for (int kt = 0; kt < 4; ++kt) {
            uint32_t vcol = ((uint32_t)((kt << 5) + (((lane >> 3) & 1) << 4))) ^ rXor;
#pragma unroll
            for (int ntp = 0; ntp < 4; ++ntp) {
                int row = hv * 64 + ntp * 16 + ntSel * 8 + r8;
                uint32_t addr = sb + VHo + (uint32_t)(row * 128) + vcol;
                uint32_t bh4[4], bl4[4];
                ldsm4(bh4, addr);
                ldsm4(bl4, addr + (VLo - VHo));
                mma16816(z[2 * ntp], pfh + 4 * kt, bh4);
                mma16816(z[2 * ntp], pfh + 4 * kt, bl4);
                mma16816(z[2 * ntp], pfl + 4 * kt, bh4);
                mma16816(z[2 * ntp + 1], pfh + 4 * kt, bh4 + 2);
                mma16816(z[2 * ntp + 1], pfh + 4 * kt, bl4 + 2);
                mma16816(z[2 * ntp + 1], pfl + 4 * kt, bh4 + 2);
            }
        }
#pragma unroll
        for (int nt = 0; nt < 8; ++nt) {
            int cq = 4 * nt + (lane & 3);
            tbu[trow * TBU_S + cq]       = pack2h(z[nt][0], z[nt][1]);
            tbu[(trow + 8) * TBU_S + cq] = pack2h(z[nt][2], z[nt][3]);
        }
        __syncthreads();
#pragma unroll
        for (int it = 0; it < 8; ++it) {
            int idx = tid + (it << 7);
            int t = idx >> 4, cqp = idx & 15;
            uint2 u = *reinterpret_cast<const uint2*>(tbu + t * TBU_S + 2 * cqp);
            __stcs(reinterpret_cast<uint2*>(zg + t * 128 + hv * 64 + 4 * cqp), u);
        }
        __syncthreads();
    }
}

// ---- merge v5: static 4-contributor form, zero-pad edges (36.5us, frozen) ----
__global__ __launch_bounds__(256)
void merge_kernel(float* __restrict__ out)
{
    __shared__ float acc[128 * 65];
    const int h = blockIdx.x & 127;
    const int b = (blockIdx.x >> 7) & 7;
    const int cch = blockIdx.x >> 10;
    const int tid = threadIdx.x, wp = tid >> 5, lane = tid & 31;
    const __half2* zb2 = reinterpret_cast<const __half2*>(g_zbuf);
    const __half2* zp = reinterpret_cast<const __half2*>(g_zpad) + lane;

    const int phb = h >> 2, pha = phb - 1;
    const bool phaV = (pha >= 0), phbV = (phb <= 30);
    const size_t BA = phaV ? ((size_t)(b * NPP + pha * NWIN) * 4096
                              + (size_t)((h & 3) + 4) * 512 + cch * 32 + lane) : 0;
    const size_t BB = phbV ? ((size_t)(b * NPP + phb * NWIN) * 4096
                              + (size_t)(h & 3) * 512 + cch * 32 + lane) : 0;

#pragma unroll
    for (int wi = 0; wi < 16; ++wi) {
        const int w = wp * 16 + wi;
        const int pwb = w >> 2, pwa = pwb - 1;
        const bool pwaV = (pwa >= 0), pwbV = (pwb <= 30);
        const size_t woff = (size_t)w * 64;
        const size_t offA = woff + (size_t)pwa * 3840;
        const size_t offB = woff + (size_t)pwb * 3840;

        const __half2* p0 = (phaV && pwaV) ? zb2 + BA + offA : zp;
        const __half2* p1 = (phaV && pwbV) ? zb2 + BA + offB : zp;
        const __half2* p2 = (phbV && pwaV) ? zb2 + BB + offA : zp;
        const __half2* p3 = (phbV && pwbV) ? zb2 + BB + offB : zp;

        __half2 v0 = __ldcs(p0), v1 = __ldcs(p1), v2 = __ldcs(p2), v3 = __ldcs(p3);
        float2 f0 = __half22float2(v0), f1 = __half22float2(v1);
        float2 f2 = __half22float2(v2), f3 = __half22float2(v3);
        acc[w * 65 + 2 * lane]     = (f0.x + f1.x) + (f2.x + f3.x);
        acc[w * 65 + 2 * lane + 1] = (f0.y + f1.y) + (f2.y + f3.y);
    }
    __syncthreads();

    const int w = tid & 127, cb = (tid >> 7) * 32;
    float* op = out + ((size_t)(b * 128 + cch * 64 + cb) * 128 + h) * 128 + w;
#pragma unroll 8
    for (int ci = 0; ci < 32; ++ci)
        op[(size_t)ci * HW] = acc[w * 65 + cb + ci];
}

extern "C" void kernel_launch(void* const* d_in, const int* in_sizes, int n_in,
                              void* d_out, int out_size)
{
    const float* q = (const float*)d_in[0];
    const float* k = (const float*)d_in[1];
    const float* v = (const float*)d_in[2];
    float* out = (float*)d_out;

    cudaFuncSetAttribute(attn_kernel,
                         cudaFuncAttributeMaxDynamicSharedMemorySize, SMEM_TOTAL);
    attn_kernel<<<NPATCH, 128, SMEM_TOTAL>>>(q, k, v);
    merge_kernel<<<8 * 128 * 2, 256>>>(out);
}

// round 16
// speedup vs baseline: 1.2755x; 1.2755x over previous
#include <cuda_runtime.h>
#include <cuda_bf16.h>
#include <cuda_fp16.h>
#include <cstdint>

constexpr int CC = 128, HH = 128, WW = 128, HW = HH * WW;
constexpr int NWIN = 31, NPP = NWIN * NWIN, NPATCH = 8 * NPP;   // 7688
constexpr float SCALE = 0.08838834764831845f;                    // 128^-0.5

constexpr int QHc = 0, QLc = 8192, KHc = 16384, KLc = 24576;
constexpr int VHo = 0, VLo = 16384, TBo = 32768;
constexpr int TBU_S = 34;
constexpr int SMEM_TOTAL = TBo + 64 * TBU_S * 4;                 // 41472

__device__ __half g_zbuf[(size_t)NPATCH * 64 * 128];             // [patch][t][c], fp16
__device__ __half g_zpad[128];                                   // zeros for edge contributors

__device__ __forceinline__ uint32_t smem_u32(const void* p) {
    uint32_t a;
    asm("{ .reg .u64 t; cvta.to.shared.u64 t, %1; cvt.u32.u64 %0, t; }" : "=r"(a) : "l"(p));
    return a;
}
__device__ __forceinline__ uint32_t sw128(uint32_t off) { return off ^ ((off >> 3) & 0x70); }
__device__ __forceinline__ void sts64(uint32_t a, uint32_t v0, uint32_t v1) {
    asm volatile("st.shared.v2.b32 [%0], {%1, %2};" :: "r"(a), "r"(v0), "r"(v1) : "memory");
}
__device__ __forceinline__ void ldsm4t(uint32_t r[4], uint32_t a) {
    asm volatile("ldmatrix.sync.aligned.m8n8.x4.trans.shared.b16 {%0,%1,%2,%3}, [%4];"
                 : "=r"(r[0]), "=r"(r[1]), "=r"(r[2]), "=r"(r[3]) : "r"(a));
}
__device__ __forceinline__ void ldsm4(uint32_t r[4], uint32_t a) {
    asm volatile("ldmatrix.sync.aligned.m8n8.x4.shared.b16 {%0,%1,%2,%3}, [%4];"
                 : "=r"(r[0]), "=r"(r[1]), "=r"(r[2]), "=r"(r[3]) : "r"(a));
}
__device__ __forceinline__ void mma16816(float c[4], const uint32_t a[4], const uint32_t b[2]) {
    asm volatile(
        "mma.sync.aligned.m16n8k16.row.col.f32.bf16.bf16.f32 "
        "{%0,%1,%2,%3}, {%4,%5,%6,%7}, {%8,%9}, {%0,%1,%2,%3};"
        : "+f"(c[0]), "+f"(c[1]), "+f"(c[2]), "+f"(c[3])
        : "r"(a[0]), "r"(a[1]), "r"(a[2]), "r"(a[3]), "r"(b[0]), "r"(b[1]));
}
__device__ __forceinline__ uint32_t pack2h(float x, float y) {
    __half2 h = __floats2half2_rn(x, y);
    return *reinterpret_cast<uint32_t*>(&h);
}
__device__ __forceinline__ void split2(float x, float y, uint32_t& hi, uint32_t& lo) {
    __nv_bfloat162 h = __floats2bfloat162_rn(x, y);
    float2 hf = __bfloat1622float2(h);
    __nv_bfloat162 l = __floats2bfloat162_rn(x - hf.x, y - hf.y);
    hi = *reinterpret_cast<uint32_t*>(&h);
    lo = *reinterpret_cast<uint32_t*>(&l);
}

__global__ __launch_bounds__(128, 4)
void attn_kernel(const float* __restrict__ q, const float* __restrict__ k,
                 const float* __restrict__ v)
{
    extern __shared__ char smem[];
    const uint32_t sb = smem_u32(smem);
    const int tid = threadIdx.x, wp = tid >> 5, lane = tid & 31;
    const int g = blockIdx.x;
    const int b = g / NPP, rr = g - b * NPP;
    const int h0 = (rr / NWIN) * 4, w0 = (rr % NWIN) * 4;
    const size_t pbase = (size_t)b * CC * HW + (size_t)h0 * WW + w0;

    const int r8 = lane & 7, mi4 = lane >> 3;
    const int dmA = (mi4 & 1) << 3, dkA = (mi4 & 2) << 2;
    const uint32_t aXor = ((uint32_t)(32 * wp + 2 * dmA)) ^ ((uint32_t)r8 << 4);
    const int rowB = ((lane >> 3) & 1) * 8 + r8;
    const int ntSel = lane >> 4;
    const uint32_t rXor = (uint32_t)r8 << 4;

    float s[8][4];
#pragma unroll
    for (int i = 0; i < 8; ++i)
#pragma unroll
        for (int j = 0; j < 4; ++j) s[i][j] = 0.f;

    // ================= phase 1: S = Q K^T, two 64-channel chunks =================
    for (int ck = 0; ck < 2; ++ck) {
#pragma unroll
        for (int it = 0; it < 8; ++it) {
            int idx = tid + (it << 7);
            int cL = idx >> 4, t0 = (idx & 15) << 2;
            int c = ck * 64 + cL;
            size_t gp = pbase + (size_t)c * HW + (size_t)(t0 >> 3) * WW + (t0 & 7);
            float4 qv = *(const float4*)(q + gp);
            float4 kv = *(const float4*)(k + gp);
            uint32_t qh0, ql0, qh1, ql1, kh0, kl0, kh1, kl1;
            split2(qv.x * SCALE, qv.y * SCALE, qh0, ql0);
            split2(qv.z * SCALE, qv.w * SCALE, qh1, ql1);
            split2(kv.x, kv.y, kh0, kl0);
            split2(kv.z, kv.w, kh1, kl1);
            uint32_t off = sw128((uint32_t)(cL * 128 + t0 * 2));
            sts64(sb + QHc + off, qh0, qh1);
            sts64(sb + QLc + off, ql0, ql1);
            sts64(sb + KHc + off, kh0, kh1);
            sts64(sb + KLc + off, kl0, kl1);
        }
        __syncthreads();
#pragma unroll
        for (int kt = 0; kt < 4; ++kt) {
            uint32_t ah[4], al[4];
            uint32_t aA = sb + QHc + (uint32_t)((kt * 16 + dkA + r8) * 128) + aXor;
            ldsm4t(ah, aA);
            ldsm4t(al, aA + (QLc - QHc));
            uint32_t bRowA = sb + KHc + (uint32_t)((kt * 16 + rowB) * 128);
#pragma unroll
            for (int ntp = 0; ntp < 4; ++ntp) {
                uint32_t bh4[4], bl4[4];
                uint32_t baddr = bRowA + ((((uint32_t)(ntp * 2 + ntSel)) << 4) ^ rXor);
                ldsm4t(bh4, baddr);
                ldsm4t(bl4, baddr + (KLc - KHc));
                mma16816(s[2 * ntp], ah, bh4);
                mma16816(s[2 * ntp], ah, bl4);
                mma16816(s[2 * ntp], al, bh4);
                mma16816(s[2 * ntp + 1], ah, bh4 + 2);
                mma16816(s[2 * ntp + 1], ah, bl4 + 2);
                mma16816(s[2 * ntp + 1], al, bh4 + 2);
            }
        }
        __syncthreads();
    }

    // ---- load V [c][s] hi/lo (aliases phase-1 buffers) ----
#pragma unroll
    for (int it = 0; it < 16; ++it) {
        int idx = tid + (it << 7);
        int c = idx >> 4, t0 = (idx & 15) << 2;
        size_t gp = pbase + (size_t)c * HW + (size_t)(t0 >> 3) * WW + (t0 & 7);
        float4 vv = *(const float4*)(v + gp);
        uint32_t vh0, vl0, vh1, vl1;
        split2(vv.x, vv.y, vh0, vl0);
        split2(vv.z, vv.w, vh1, vl1);
        uint32_t off = sw128((uint32_t)(c * 128 + t0 * 2));
        sts64(sb + VHo + off, vh0, vh1);
        sts64(sb + VLo + off, vl0, vl1);
    }

    // ---- softmax in registers (row lives in 4 lanes) ----
    float mx0 = -1e30f, mx1 = -1e30f;
#pragma unroll
    for (int nt = 0; nt < 8; ++nt) {
        mx0 = fmaxf(mx0, fmaxf(s[nt][0], s[nt][1]));
        mx1 = fmaxf(mx1, fmaxf(s[nt][2], s[nt][3]));
    }
    mx0 = fmaxf(mx0, __shfl_xor_sync(~0u, mx0, 1));
    mx0 = fmaxf(mx0, __shfl_xor_sync(~0u, mx0, 2));
    mx1 = fmaxf(mx1, __shfl_xor_sync(~0u, mx1, 1));
    mx1 = fmaxf(mx1, __shfl_xor_sync(~0u, mx1, 2));
    float sm0 = 0.f, sm1 = 0.f;
#pragma unroll
    for (int nt = 0; nt < 8; ++nt) {
        s[nt][0] = __expf(s[nt][0] - mx0);
        s[nt][1] = __expf(s[nt][1] - mx0);
        s[nt][2] = __expf(s[nt][2] - mx1);
        s[nt][3] = __expf(s[nt][3] - mx1);
        sm0 += s[nt][0] + s[nt][1];
        sm1 += s[nt][2] + s[nt][3];
    }
    sm0 += __shfl_xor_sync(~0u, sm0, 1);
    sm0 += __shfl_xor_sync(~0u, sm0, 2);
    sm1 += __shfl_xor_sync(~0u, sm1, 1);
    sm1 += __shfl_xor_sync(~0u, sm1, 2);
    const float inv0 = 1.f / sm0, inv1 = 1.f / sm1;

    // ---- P fragments: split ONCE (s dies here; pf reused by both hv halves) ----
    uint32_t pfh[16], pfl[16];
#pragma unroll
    for (int kt = 0; kt < 4; ++kt) {
        split2(s[2 * kt][0] * inv0, s[2 * kt][1] * inv0, pfh[4 * kt + 0], pfl[4 * kt + 0]);
        split2(s[2 * kt][2] * inv1, s[2 * kt][3] * inv1, pfh[4 * kt + 1], pfl[4 * kt + 1]);
        split2(s[2 * kt + 1][0] * inv0, s[2 * kt + 1][1] * inv0, pfh[4 * kt + 2], pfl[4 * kt + 2]);
        split2(s[2 * kt + 1][2] * inv1, s[2 * kt + 1][3] * inv1, pfh[4 * kt + 3], pfl[4 * kt + 3]);
    }
    __syncthreads();   // V visible

    // ================= phase 2: Z = P V, two 64-channel halves =================
    uint32_t* tbu = reinterpret_cast<uint32_t*>(smem + TBo);
    __half* zg = g_zbuf + (size_t)g * 8192;
    const int trow = 16 * wp + (lane >> 2);

    for (int hv = 0; hv < 2; ++hv) {
        float z[8][4];
#pragma unroll
        for (int i = 0; i < 8; ++i)
#pragma unroll
            for (int j = 0; j < 4; ++j) z[i][j] = 0.f;

#pragma unroll
        for (int kt = 0; kt < 4; ++kt) {
            uint32_t vcol = ((uint32_t)((kt << 5) + (((lane >> 3) & 1) << 4))) ^ rXor;
#pragma unroll
            for (int ntp = 0; ntp < 4; ++ntp) {
                int row = hv * 64 + ntp * 16 + ntSel * 8 + r8;
                uint32_t addr = sb + VHo + (uint32_t)(row * 128) + vcol;
                uint32_t bh4[4], bl4[4];
                ldsm4(bh4, addr);
                ldsm4(bl4, addr + (VLo - VHo));
                mma16816(z[2 * ntp], pfh + 4 * kt, bh4);
                mma16816(z[2 * ntp], pfh + 4 * kt, bl4);
                mma16816(z[2 * ntp], pfl + 4 * kt, bh4);
                mma16816(z[2 * ntp + 1], pfh + 4 * kt, bh4 + 2);
                mma16816(z[2 * ntp + 1], pfh + 4 * kt, bl4 + 2);
                mma16816(z[2 * ntp + 1], pfl + 4 * kt, bh4 + 2);
            }
        }
#pragma unroll
        for (int nt = 0; nt < 8; ++nt) {
            int cq = 4 * nt + (lane & 3);
            tbu[trow * TBU_S + cq]       = pack2h(z[nt][0], z[nt][1]);
            tbu[(trow + 8) * TBU_S + cq] = pack2h(z[nt][2], z[nt][3]);
        }
        __syncthreads();
#pragma unroll
        for (int it = 0; it < 8; ++it) {
            int idx = tid + (it << 7);
            int t = idx >> 4, cqp = idx & 15;
            uint2 u = *reinterpret_cast<const uint2*>(tbu + t * TBU_S + 2 * cqp);
            __stcs(reinterpret_cast<uint2*>(zg + t * 128 + hv * 64 + 4 * cqp), u);
        }
        __syncthreads();
    }
}

// ---- merge v5: static 4-contributor form, zero-pad edges (36.5us, frozen) ----
__global__ __launch_bounds__(256)
void merge_kernel(float* __restrict__ out)
{
    __shared__ float acc[128 * 65];
    const int h = blockIdx.x & 127;
    const int b = (blockIdx.x >> 7) & 7;
    const int cch = blockIdx.x >> 10;
    const int tid = threadIdx.x, wp = tid >> 5, lane = tid & 31;
    const __half2* zb2 = reinterpret_cast<const __half2*>(g_zbuf);
    const __half2* zp = reinterpret_cast<const __half2*>(g_zpad) + lane;

    const int phb = h >> 2, pha = phb - 1;
    const bool phaV = (pha >= 0), phbV = (phb <= 30);
    const size_t BA = phaV ? ((size_t)(b * NPP + pha * NWIN) * 4096
                              + (size_t)((h & 3) + 4) * 512 + cch * 32 + lane) : 0;
    const size_t BB = phbV ? ((size_t)(b * NPP + phb * NWIN) * 4096
                              + (size_t)(h & 3) * 512 + cch * 32 + lane) : 0;

#pragma unroll
    for (int wi = 0; wi < 16; ++wi) {
        const int w = wp * 16 + wi;
        const int pwb = w >> 2, pwa = pwb - 1;
        const bool pwaV = (pwa >= 0), pwbV = (pwb <= 30);
        const size_t woff = (size_t)w * 64;
        const size_t offA = woff + (size_t)pwa * 3840;
        const size_t offB = woff + (size_t)pwb * 3840;

        const __half2* p0 = (phaV && pwaV) ? zb2 + BA + offA : zp;
        const __half2* p1 = (phaV && pwbV) ? zb2 + BA + offB : zp;
        const __half2* p2 = (phbV && pwaV) ? zb2 + BB + offA : zp;
        const __half2* p3 = (phbV && pwbV) ? zb2 + BB + offB : zp;

        __half2 v0 = __ldcs(p0), v1 = __ldcs(p1), v2 = __ldcs(p2), v3 = __ldcs(p3);
        float2 f0 = __half22float2(v0), f1 = __half22float2(v1);
        float2 f2 = __half22float2(v2), f3 = __half22float2(v3);
        acc[w * 65 + 2 * lane]     = (f0.x + f1.x) + (f2.x + f3.x);
        acc[w * 65 + 2 * lane + 1] = (f0.y + f1.y) + (f2.y + f3.y);
    }
    __syncthreads();

    const int w = tid & 127, cb = (tid >> 7) * 32;
    float* op = out + ((size_t)(b * 128 + cch * 64 + cb) * 128 + h) * 128 + w;
#pragma unroll 8
    for (int ci = 0; ci < 32; ++ci)
        op[(size_t)ci * HW] = acc[w * 65 + cb + ci];
}

extern "C" void kernel_launch(void* const* d_in, const int* in_sizes, int n_in,
                              void* d_out, int out_size)
{
    const float* q = (const float*)d_in[0];
    const float* k = (const float*)d_in[1];
    const float* v = (const float*)d_in[2];
    float* out = (float*)d_out;

    cudaFuncSetAttribute(attn_kernel,
                         cudaFuncAttributeMaxDynamicSharedMemorySize, SMEM_TOTAL);
    attn_kernel<<<NPATCH, 128, SMEM_TOTAL>>>(q, k, v);
    merge_kernel<<<8 * 128 * 2, 256>>>(out);
}